// round 1
// baseline (speedup 1.0000x reference)
#include <cuda_runtime.h>
#include <math.h>

constexpr int Bb   = 64;     // batch
constexpr int Tt   = 12;     // encoder steps
constexpr int Nn   = 1024;   // nodes
constexpr int Hh   = 64;     // hidden
constexpr int Ee   = 10;     // embedding dim
constexpr int Hor  = 12;     // decoder horizon
constexpr int FP   = 208;    // padded feature width (>= 3*66, mult of 16)
constexpr int ROWS = Nn * Bb; // 65536

// ---------------- scratch (device globals; no allocations allowed) ----------
__device__ __align__(128) float g_SS_enc[2 * Nn * Nn];   // [S ; S2] encoder
__device__ __align__(128) float g_SS_dec[2 * Nn * Nn];   // [S ; S2] decoder
__device__ __align__(128) float g_Xin[Nn * Bb * 66];     // [n, b*cdim+c]
__device__ __align__(128) float g_F[ROWS * FP];          // [(n*64+b), 208]
__device__ __align__(128) float g_ZR[ROWS * 128];        // raw gate GEMM out
__device__ __align__(128) float g_HC[ROWS * 64];         // raw cand GEMM out
__device__ __align__(128) float g_h[ROWS * 64];          // state [n*64+b, h]
__device__ __align__(128) float g_go[ROWS];
__device__ __align__(128) float g_demb[Nn * Bb * Ee];    // [1024, 640]
__device__ __align__(128) float g_dembT[Bb * Ee * Nn];   // [640, 1024]
__device__ __align__(128) float g_embpad[Nn * 16];
__device__ __align__(128) float g_embpadT[16 * Nn];
__device__ __align__(128) float g_Wg_enc[FP * 128];
__device__ __align__(128) float g_Wu_enc[FP * 64];
__device__ __align__(128) float g_Wg_dec[FP * 128];
__device__ __align__(128) float g_Wu_dec[FP * 64];

__device__ __forceinline__ float sigmoidf_(float x) { return 1.0f / (1.0f + expf(-x)); }

// ---------------- generic SGEMM: C = A(MxK) @ B(KxN), row-major -------------
// MODE 0: plain row-major store into C (ldc = N)
// MODE 1/2: scatter into g_F: row m -> (k=m>>10, n=m&1023), col j -> (b=j/CDIM,
//           c=j%CDIM); F[(n*64+b)*208 + (k+1)*CDIM + c] = val   (CDIM=65/66)
// Requires M%128==0, N%64==0, K%16==0 (guaranteed by construction).
template <int MODE, int CDIM>
__global__ void __launch_bounds__(256) sgemm_kernel(
    const float* __restrict__ A, const float* __restrict__ B,
    float* __restrict__ C, int M, int N, int K)
{
    constexpr int BM = 128, BN = 64, BK = 16;
    __shared__ __align__(16) float As[BK][BM];
    __shared__ __align__(16) float Bs[BK][BN];

    const int tid = threadIdx.x;
    const int tx = tid & 15;      // -> 4 cols each
    const int ty = tid >> 4;      // -> 8 rows each
    const int m0 = blockIdx.y * BM;
    const int n0 = blockIdx.x * BN;

    float acc[8][4];
#pragma unroll
    for (int i = 0; i < 8; i++)
#pragma unroll
        for (int j = 0; j < 4; j++) acc[i][j] = 0.0f;

    const int arow0 = tid >> 2;          // 0..63 (+64 second pass)
    const int acol0 = (tid & 3) * 4;     // 0,4,8,12
    const int brow  = tid >> 4;          // 0..15
    const int bcol  = (tid & 15) * 4;    // 0..60

    for (int kt = 0; kt < K; kt += BK) {
#pragma unroll
        for (int i = 0; i < 2; i++) {
            int r = arow0 + i * 64;
            float4 v = *reinterpret_cast<const float4*>(
                A + (size_t)(m0 + r) * K + kt + acol0);
            As[acol0 + 0][r] = v.x;
            As[acol0 + 1][r] = v.y;
            As[acol0 + 2][r] = v.z;
            As[acol0 + 3][r] = v.w;
        }
        float4 bv = *reinterpret_cast<const float4*>(
            B + (size_t)(kt + brow) * N + n0 + bcol);
        *reinterpret_cast<float4*>(&Bs[brow][bcol]) = bv;
        __syncthreads();

#pragma unroll
        for (int k = 0; k < BK; k++) {
            float4 a0 = *reinterpret_cast<const float4*>(&As[k][ty * 8]);
            float4 a1 = *reinterpret_cast<const float4*>(&As[k][ty * 8 + 4]);
            float4 b0 = *reinterpret_cast<const float4*>(&Bs[k][tx * 4]);
            float am[8] = {a0.x, a0.y, a0.z, a0.w, a1.x, a1.y, a1.z, a1.w};
            float bn[4] = {b0.x, b0.y, b0.z, b0.w};
#pragma unroll
            for (int i = 0; i < 8; i++)
#pragma unroll
                for (int j = 0; j < 4; j++)
                    acc[i][j] = fmaf(am[i], bn[j], acc[i][j]);
        }
        __syncthreads();
    }

    if (MODE == 0) {
#pragma unroll
        for (int i = 0; i < 8; i++) {
            int m = m0 + ty * 8 + i;
            float4 v = make_float4(acc[i][0], acc[i][1], acc[i][2], acc[i][3]);
            *reinterpret_cast<float4*>(C + (size_t)m * N + n0 + tx * 4) = v;
        }
    } else {
#pragma unroll
        for (int i = 0; i < 8; i++) {
            int m = m0 + ty * 8 + i;
            int kk = m >> 10;
            int n  = m & 1023;
#pragma unroll
            for (int j = 0; j < 4; j++) {
                int col = n0 + tx * 4 + j;
                int b = col / CDIM;
                int c = col - b * CDIM;
                C[(size_t)((n << 6) + b) * FP + (kk + 1) * CDIM + c] = acc[i][j];
            }
        }
    }
}

// ---------------- small helper kernels --------------------------------------
__global__ void k_zero(float* p, int n) {
    int i = blockIdx.x * blockDim.x + threadIdx.x;
    if (i < n) p[i] = 0.0f;
}

__global__ void k_pad_emb(const float* __restrict__ emb) {
    int idx = blockIdx.x * blockDim.x + threadIdx.x;
    if (idx >= Nn * 16) return;
    int n = idx >> 4, j = idx & 15;
    g_embpad[idx] = (j < Ee) ? emb[n * Ee + j] : 0.0f;
}

__global__ void k_transpose(const float* __restrict__ in, float* __restrict__ out,
                            int R, int C) {
    int idx = blockIdx.x * blockDim.x + threadIdx.x;
    if (idx >= R * C) return;
    int r = idx / C, c = idx - r * C;
    out[c * R + r] = in[idx];
}

__global__ void k_pad_copy(const float* __restrict__ src, float* __restrict__ dst,
                           int rows, int cols) {
    int idx = blockIdx.x * blockDim.x + threadIdx.x;
    if (idx >= FP * cols) return;
    dst[idx] = (idx < rows * cols) ? src[idx] : 0.0f;
}

// softmax(relu(row)) over 1024 cols, one block (256 thr) per row, in-place
__global__ void k_relu_softmax(float* __restrict__ S) {
    int row = blockIdx.x;
    float* p = S + (size_t)row * Nn;
    int t = threadIdx.x;
    float v[4];
#pragma unroll
    for (int i = 0; i < 4; i++) {
        float x = p[t + i * 256];
        v[i] = x > 0.0f ? x : 0.0f;
    }
    __shared__ float red[256];
    float m = fmaxf(fmaxf(v[0], v[1]), fmaxf(v[2], v[3]));
    red[t] = m;
    __syncthreads();
    for (int s = 128; s > 0; s >>= 1) {
        if (t < s) red[t] = fmaxf(red[t], red[t + s]);
        __syncthreads();
    }
    m = red[0];
    __syncthreads();
    float e[4], sum = 0.0f;
#pragma unroll
    for (int i = 0; i < 4; i++) {
        e[i] = expf(v[i] - m);
        sum += e[i];
    }
    red[t] = sum;
    __syncthreads();
    for (int s = 128; s > 0; s >>= 1) {
        if (t < s) red[t] += red[t + s];
        __syncthreads();
    }
    float inv = 1.0f / red[0];
#pragma unroll
    for (int i = 0; i < 4; i++) p[t + i * 256] = e[i] * inv;
}

// P := 2*P - I  (in place, [1024,1024])
__global__ void k_cheb(float* __restrict__ P) {
    int idx = blockIdx.x * blockDim.x + threadIdx.x;
    if (idx >= Nn * Nn) return;
    int r = idx >> 10, c = idx & 1023;
    P[idx] = 2.0f * P[idx] - (r == c ? 1.0f : 0.0f);
}

// encoder xin = [x_t, h] -> Xin [n, b*65+c] and F cols 0..64
__global__ void k_build_xin_enc(const float* __restrict__ x, int t) {
    int idx = blockIdx.x * blockDim.x + threadIdx.x;
    if (idx >= ROWS * 64) return;
    int id = idx >> 6, i = idx & 63;
    int n = id >> 6, b = id & 63;
    float hv = g_h[idx];
    g_Xin[(size_t)n * (64 * 65) + b * 65 + 1 + i] = hv;
    g_F[(size_t)id * FP + 1 + i] = hv;
    if (i == 0) {
        float xv = x[((size_t)b * Tt + t) * Nn + n];
        g_Xin[(size_t)n * (64 * 65) + b * 65] = xv;
        g_F[(size_t)id * FP] = xv;
    }
}

// decoder xin = [go, ycov_t, h]
__global__ void k_build_xin_dec(const float* __restrict__ ycov, int t) {
    int idx = blockIdx.x * blockDim.x + threadIdx.x;
    if (idx >= ROWS * 64) return;
    int id = idx >> 6, i = idx & 63;
    int n = id >> 6, b = id & 63;
    float hv = g_h[idx];
    g_Xin[(size_t)n * (64 * 66) + b * 66 + 2 + i] = hv;
    g_F[(size_t)id * FP + 2 + i] = hv;
    if (i == 0) {
        float gv = g_go[id];
        float yv = ycov[((size_t)b * Hor + t) * Nn + n];
        g_Xin[(size_t)n * (64 * 66) + b * 66] = gv;
        g_Xin[(size_t)n * (64 * 66) + b * 66 + 1] = yv;
        g_F[(size_t)id * FP] = gv;
        g_F[(size_t)id * FP + 1] = yv;
    }
}

// z = sigmoid(ZR[:,:64]+bg[:64]); write z*h into Xin/F state slots
template <int CDIM>
__global__ void k_gate_epi(const float* __restrict__ bg) {
    int idx = blockIdx.x * blockDim.x + threadIdx.x;
    if (idx >= ROWS * 64) return;
    int id = idx >> 6, i = idx & 63;
    int n = id >> 6, b = id & 63;
    float z = sigmoidf_(g_ZR[(size_t)id * 128 + i] + bg[i]);
    float v = z * g_h[idx];
    int off = CDIM - 64;
    g_Xin[(size_t)n * (64 * CDIM) + b * CDIM + off + i] = v;
    g_F[(size_t)id * FP + off + i] = v;
}

// r = sigmoid(ZR[:,64:]+bg[64:]); h = r*h + (1-r)*tanh(HC+bu)
__global__ void k_update_epi(const float* __restrict__ bg, const float* __restrict__ bu) {
    int idx = blockIdx.x * blockDim.x + threadIdx.x;
    if (idx >= ROWS * 64) return;
    int id = idx >> 6, i = idx & 63;
    float r = sigmoidf_(g_ZR[(size_t)id * 128 + 64 + i] + bg[64 + i]);
    float hc = tanhf(g_HC[idx] + bu[i]);
    float h = g_h[idx];
    g_h[idx] = r * h + (1.0f - r) * hc;
}

// dec_emb = h @ FC_E  -> g_demb [1024, 64*10]
__global__ void k_demb(const float* __restrict__ fce) {
    int idx = blockIdx.x * blockDim.x + threadIdx.x;
    if (idx >= ROWS * Ee) return;
    int id = idx / Ee, e = idx - id * Ee;
    const float* hr = g_h + (size_t)id * 64;
    float s = 0.0f;
#pragma unroll
    for (int h = 0; h < 64; h++) s = fmaf(hr[h], fce[h * Ee + e], s);
    g_demb[idx] = s;
}

__global__ void k_init_go(const float* __restrict__ x) {
    int id = blockIdx.x * blockDim.x + threadIdx.x;
    if (id >= ROWS) return;
    int n = id >> 6, b = id & 63;
    g_go[id] = x[((size_t)b * Tt + (Tt - 1)) * Nn + n];
}

// go = h @ proj_w + pb ; write output[b, t, n]
__global__ void k_proj_out(const float* __restrict__ pw, const float* __restrict__ pb,
                           float* __restrict__ out, int t) {
    int id = blockIdx.x * blockDim.x + threadIdx.x;
    if (id >= ROWS) return;
    int n = id >> 6, b = id & 63;
    const float* hr = g_h + (size_t)id * 64;
    float s = pb[0];
#pragma unroll
    for (int i = 0; i < 64; i++) s = fmaf(hr[i], pw[i], s);
    g_go[id] = s;
    out[((size_t)b * Hor + t) * Nn + n] = s;
}

// ---------------- orchestration ---------------------------------------------
extern "C" void kernel_launch(void* const* d_in, const int* in_sizes, int n_in,
                              void* d_out, int out_size) {
    const float* x    = (const float*)d_in[0];
    const float* ycov = (const float*)d_in[1];
    const float* emb  = (const float*)d_in[2];
    const float* fce  = (const float*)d_in[3];
    const float* egw  = (const float*)d_in[4];
    const float* egb  = (const float*)d_in[5];
    const float* euw  = (const float*)d_in[6];
    const float* eub  = (const float*)d_in[7];
    const float* dgw  = (const float*)d_in[8];
    const float* dgb  = (const float*)d_in[9];
    const float* duw  = (const float*)d_in[10];
    const float* dub  = (const float*)d_in[11];
    const float* pw   = (const float*)d_in[12];
    const float* pb   = (const float*)d_in[13];
    float* out = (float*)d_out;

    float *pSSe, *pSSd, *pXin, *pF, *pZR, *pHC, *ph;
    float *pDemb, *pDembT, *pEp, *pEpT, *pWge, *pWue, *pWgd, *pWud;
    cudaGetSymbolAddress((void**)&pSSe, g_SS_enc);
    cudaGetSymbolAddress((void**)&pSSd, g_SS_dec);
    cudaGetSymbolAddress((void**)&pXin, g_Xin);
    cudaGetSymbolAddress((void**)&pF, g_F);
    cudaGetSymbolAddress((void**)&pZR, g_ZR);
    cudaGetSymbolAddress((void**)&pHC, g_HC);
    cudaGetSymbolAddress((void**)&ph, g_h);
    cudaGetSymbolAddress((void**)&pDemb, g_demb);
    cudaGetSymbolAddress((void**)&pDembT, g_dembT);
    cudaGetSymbolAddress((void**)&pEp, g_embpad);
    cudaGetSymbolAddress((void**)&pEpT, g_embpadT);
    cudaGetSymbolAddress((void**)&pWge, g_Wg_enc);
    cudaGetSymbolAddress((void**)&pWue, g_Wu_enc);
    cudaGetSymbolAddress((void**)&pWgd, g_Wg_dec);
    cudaGetSymbolAddress((void**)&pWud, g_Wu_dec);

    // ---- setup
    k_zero<<<ROWS * FP / 256, 256>>>(pF, ROWS * FP);
    k_zero<<<ROWS * 64 / 256, 256>>>(ph, ROWS * 64);
    k_pad_emb<<<64, 256>>>(emb);
    k_transpose<<<64, 256>>>(pEp, pEpT, Nn, 16);
    k_pad_copy<<<104, 256>>>(egw, pWge, 195, 128);
    k_pad_copy<<<52, 256>>>(euw, pWue, 195, 64);
    k_pad_copy<<<104, 256>>>(dgw, pWgd, 198, 128);
    k_pad_copy<<<52, 256>>>(duw, pWud, 198, 64);

    // encoder supports: S then S2 = 2*S@S - I
    sgemm_kernel<0, 1><<<dim3(16, 8), 256>>>(pEp, pEpT, pSSe, Nn, Nn, 16);
    k_relu_softmax<<<Nn, 256>>>(pSSe);
    sgemm_kernel<0, 1><<<dim3(16, 8), 256>>>(pSSe, pSSe, pSSe + Nn * Nn, Nn, Nn, Nn);
    k_cheb<<<Nn * Nn / 256, 256>>>(pSSe + Nn * Nn);

    // ---- encoder
    for (int t = 0; t < Tt; t++) {
        k_build_xin_enc<<<16384, 256>>>(x, t);
        sgemm_kernel<1, 65><<<dim3(65, 16), 256>>>(pSSe, pXin, pF, 2048, 64 * 65, Nn);
        sgemm_kernel<0, 1><<<dim3(2, 512), 256>>>(pF, pWge, pZR, ROWS, 128, FP);
        k_gate_epi<65><<<16384, 256>>>(egb);
        sgemm_kernel<1, 65><<<dim3(65, 16), 256>>>(pSSe, pXin, pF, 2048, 64 * 65, Nn);
        sgemm_kernel<0, 1><<<dim3(1, 512), 256>>>(pF, pWue, pHC, ROWS, 64, FP);
        k_update_epi<<<16384, 256>>>(egb, eub);
    }

    // decoder supports from dec_emb gram (sum over batch)
    k_demb<<<ROWS * Ee / 256, 256>>>(fce);
    k_transpose<<<ROWS * Ee / 256, 256>>>(pDemb, pDembT, Nn, Bb * Ee);
    sgemm_kernel<0, 1><<<dim3(16, 8), 256>>>(pDemb, pDembT, pSSd, Nn, Nn, Bb * Ee);
    k_relu_softmax<<<Nn, 256>>>(pSSd);
    sgemm_kernel<0, 1><<<dim3(16, 8), 256>>>(pSSd, pSSd, pSSd + Nn * Nn, Nn, Nn, Nn);
    k_cheb<<<Nn * Nn / 256, 256>>>(pSSd + Nn * Nn);
    k_init_go<<<256, 256>>>(x);

    // ---- decoder
    for (int t = 0; t < Hor; t++) {
        k_build_xin_dec<<<16384, 256>>>(ycov, t);
        sgemm_kernel<2, 66><<<dim3(66, 16), 256>>>(pSSd, pXin, pF, 2048, 64 * 66, Nn);
        sgemm_kernel<0, 1><<<dim3(2, 512), 256>>>(pF, pWgd, pZR, ROWS, 128, FP);
        k_gate_epi<66><<<16384, 256>>>(dgb);
        sgemm_kernel<2, 66><<<dim3(66, 16), 256>>>(pSSd, pXin, pF, 2048, 64 * 66, Nn);
        sgemm_kernel<0, 1><<<dim3(1, 512), 256>>>(pF, pWud, pHC, ROWS, 64, FP);
        k_update_epi<<<16384, 256>>>(dgb, dub);
        k_proj_out<<<256, 256>>>(pw, pb, out, t);
    }
}